// round 3
// baseline (speedup 1.0000x reference)
#include <cuda_runtime.h>
#include <math.h>

#define BB   4
#define LL   4096
#define DIMN 1024
#define HH   16
#define HD   64
#define DI   4
#define CH   16
#define NC   (LL / CH)
#define MTOT (BB * LL)

// ---------------- scratch (no cudaMalloc allowed; buffers chain-reused) ----
__device__ float g_b0[(size_t)MTOT * DIMN];   // qlin -> k(conv)
__device__ float g_b1[(size_t)MTOT * DIMN];   // klin -> v(conv)
__device__ float g_b2[(size_t)MTOT * DIMN];   // vlin -> omid
__device__ float g_b3[(size_t)MTOT * DIMN];   // glin (gate)
__device__ float g_b4[(size_t)MTOT * DIMN];   // q(conv)
__device__ float g_lr[(size_t)MTOT * 32];

// ---------------- SGEMM: C[M,N] = A[M,K] @ B[N,K]^T (both row-major) ----
// 128x128 tile, BK=8, 256 threads, 8x8 per-thread microtile.
__global__ __launch_bounds__(256) void sgemm_nt(const float* __restrict__ A,
                                                const float* __restrict__ B,
                                                float* __restrict__ C,
                                                int M, int N, int K) {
    __shared__ float As[8][132];
    __shared__ float Bs[8][132];
    int tid = threadIdx.x;
    int bm = blockIdx.y * 128, bn = blockIdx.x * 128;
    int lrow = tid >> 1, lcol = (tid & 1) * 4;
    const float* Ag = A + (size_t)(bm + lrow) * K + lcol;
    const float* Bg = B + (size_t)(bn + lrow) * K + lcol;
    int tx = tid & 15, ty = tid >> 4;

    float acc[8][8];
#pragma unroll
    for (int i = 0; i < 8; i++)
#pragma unroll
        for (int j = 0; j < 8; j++) acc[i][j] = 0.f;

    for (int k0 = 0; k0 < K; k0 += 8) {
        float4 av = *(const float4*)(Ag + k0);
        float4 bv = *(const float4*)(Bg + k0);
        __syncthreads();
        As[lcol + 0][lrow] = av.x; As[lcol + 1][lrow] = av.y;
        As[lcol + 2][lrow] = av.z; As[lcol + 3][lrow] = av.w;
        Bs[lcol + 0][lrow] = bv.x; Bs[lcol + 1][lrow] = bv.y;
        Bs[lcol + 2][lrow] = bv.z; Bs[lcol + 3][lrow] = bv.w;
        __syncthreads();
#pragma unroll
        for (int kk = 0; kk < 8; kk++) {
            float ra[8], rb[8];
            *(float4*)&ra[0] = *(const float4*)&As[kk][ty * 8];
            *(float4*)&ra[4] = *(const float4*)&As[kk][ty * 8 + 4];
            *(float4*)&rb[0] = *(const float4*)&Bs[kk][tx * 8];
            *(float4*)&rb[4] = *(const float4*)&Bs[kk][tx * 8 + 4];
#pragma unroll
            for (int i = 0; i < 8; i++)
#pragma unroll
                for (int j = 0; j < 8; j++) acc[i][j] += ra[i] * rb[j];
        }
    }
#pragma unroll
    for (int i = 0; i < 8; i++) {
        int row = bm + ty * 8 + i;
        float* Cp = C + (size_t)row * N + bn + tx * 8;
        *(float4*)Cp       = make_float4(acc[i][0], acc[i][1], acc[i][2], acc[i][3]);
        *(float4*)(Cp + 4) = make_float4(acc[i][4], acc[i][5], acc[i][6], acc[i][7]);
    }
}

// ---------------- lr = softplus(hs @ Wlr^T + 1e-3), (MTOT x 32) -----------
__global__ __launch_bounds__(256) void lr_gemm(const float* __restrict__ X,
                                               const float* __restrict__ W,
                                               float* __restrict__ out) {
    int r = blockIdx.x * 8 + (threadIdx.x >> 5);
    int n = threadIdx.x & 31;
    const float* x = X + (size_t)r * DIMN;
    const float* w = W + (size_t)n * DIMN;
    float acc = 0.f;
    for (int k = 0; k < DIMN; k += 4) {
        float4 xv = *(const float4*)(x + k);
        float4 wv = *(const float4*)(w + k);
        acc += xv.x * wv.x + xv.y * wv.y + xv.z * wv.z + xv.w * wv.w;
    }
    acc += 0.001f;
    float sp = fmaxf(acc, 0.f) + log1pf(expf(-fabsf(acc)));
    out[(size_t)r * 32 + n] = sp;
}

__device__ __forceinline__ float wredsum(float v) {
    for (int m = 16; m > 0; m >>= 1) v += __shfl_xor_sync(0xffffffffu, v, m);
    return v;
}

// ---------------- causal depthwise conv (K=4) + residual + silu (+l2norm) --
template <bool NORM>
__global__ __launch_bounds__(256) void conv_act(const float* __restrict__ X,
                                                const float* __restrict__ W,
                                                float* __restrict__ out) {
    __shared__ float sval[DIMN];
    __shared__ float rnorm[HH];
    int row = blockIdx.x;
    int l = row & (LL - 1);
    int tid = threadIdx.x;
    int c0 = tid * 4;
    const float4* X4 = (const float4*)X;
    size_t base = (size_t)row * (DIMN / 4) + tid;
    float4 z = make_float4(0.f, 0.f, 0.f, 0.f);
    float4 x3 = X4[base];
    float4 x2 = (l >= 1) ? X4[base - 256] : z;
    float4 x1 = (l >= 2) ? X4[base - 512] : z;
    float4 x0 = (l >= 3) ? X4[base - 768] : z;
    const float4* W4 = (const float4*)W;
    float4 wA = W4[c0 + 0], wB = W4[c0 + 1], wC = W4[c0 + 2], wD = W4[c0 + 3];

    float y0 = x3.x + wA.x * x0.x + wA.y * x1.x + wA.z * x2.x + wA.w * x3.x;
    float y1 = x3.y + wB.x * x0.y + wB.y * x1.y + wB.z * x2.y + wB.w * x3.y;
    float y2 = x3.z + wC.x * x0.z + wC.y * x1.z + wC.z * x2.z + wC.w * x3.z;
    float y3 = x3.w + wD.x * x0.w + wD.y * x1.w + wD.z * x2.w + wD.w * x3.w;
    // silu
    y0 = y0 / (1.f + expf(-y0));
    y1 = y1 / (1.f + expf(-y1));
    y2 = y2 / (1.f + expf(-y2));
    y3 = y3 / (1.f + expf(-y3));

    if (NORM) {
        sval[c0 + 0] = y0; sval[c0 + 1] = y1; sval[c0 + 2] = y2; sval[c0 + 3] = y3;
        __syncthreads();
        int wId = tid >> 5, lane = tid & 31;
        for (int h = wId; h < HH; h += 8) {
            float a = sval[h * 64 + lane];
            float b = sval[h * 64 + lane + 32];
            float s = wredsum(a * a + b * b);
            if (lane == 0) rnorm[h] = rsqrtf(s);
        }
        __syncthreads();
        float rn = rnorm[tid >> 4];
        y0 *= rn; y1 *= rn; y2 *= rn; y3 *= rn;
    }
    ((float4*)out)[base] = make_float4(y0, y1, y2, y3);
}

// ---------------- per-head layernorm + gate multiply (in place) -----------
__global__ __launch_bounds__(256) void ln_gate(float* __restrict__ o,
                                               const float* __restrict__ gate,
                                               const float* __restrict__ lng,
                                               const float* __restrict__ lnb) {
    __shared__ float sval[DIMN];
    __shared__ float smu[HH], srs[HH];
    int row = blockIdx.x;
    int tid = threadIdx.x;
    size_t base = (size_t)row * (DIMN / 4) + tid;
    float4 y = ((const float4*)o)[base];
    int c0 = tid * 4;
    sval[c0 + 0] = y.x; sval[c0 + 1] = y.y; sval[c0 + 2] = y.z; sval[c0 + 3] = y.w;
    __syncthreads();
    int wId = tid >> 5, lane = tid & 31;
    for (int h = wId; h < HH; h += 8) {
        float a = sval[h * 64 + lane];
        float b = sval[h * 64 + lane + 32];
        float s = wredsum(a + b);
        float ss = wredsum(a * a + b * b);
        if (lane == 0) {
            float mu = s * (1.f / 64.f);
            float var = ss * (1.f / 64.f) - mu * mu;
            smu[h] = mu;
            srs[h] = rsqrtf(var + 1e-5f);
        }
    }
    __syncthreads();
    int h = tid >> 4;
    float mu = smu[h], rs = srs[h];
    int d0 = c0 & 63;
    float4 gv = ((const float4*)gate)[base];
    float4 lg = ((const float4*)lng)[d0 >> 2];
    float4 lb = ((const float4*)lnb)[d0 >> 2];
    float4 r;
    r.x = ((y.x - mu) * rs * lg.x + lb.x) * gv.x;
    r.y = ((y.y - mu) * rs * lg.y + lb.y) * gv.y;
    r.z = ((y.z - mu) * rs * lg.z + lb.z) * gv.z;
    r.w = ((y.w - mu) * rs * lg.w + lb.w) * gv.w;
    ((float4*)o)[base] = r;
}

// ---------------- the sequential chunk scan -------------------------------
// One block per (b,h). 128 threads. State W_in/W_out (4x64) lives in smem.
__global__ __launch_bounds__(128) void scan_kernel(const float* __restrict__ qa,
                                                   const float* __restrict__ ka,
                                                   const float* __restrict__ va,
                                                   const float* __restrict__ lrb,
                                                   const float* __restrict__ Wini,
                                                   const float* __restrict__ Wouti,
                                                   float* __restrict__ omid) {
    __shared__ float sq[CH][HD + 1], sk[CH][HD + 1], sv[CH][HD + 1];
    __shared__ float Win[DI][HD + 1], Wout[DI][HD + 1];
    __shared__ float kh[CH][DI + 1], qh[CH][DI + 1];
    __shared__ float qkm[CH][CH + 1];
    __shared__ float p1[DI][CH + 1], p2[DI][CH + 1];
    __shared__ float lr1[CH];
    __shared__ float lr_in_s;

    int blk = blockIdx.x;
    int b = blk >> 4, h = blk & 15;
    int tid = threadIdx.x;
    const unsigned FULL = 0xffffffffu;

    for (int i = tid; i < DI * HD; i += 128) {
        int D = i >> 6, d = i & 63;
        Win[D][d]  = Wini[((size_t)D * HH + h) * HD + d];
        Wout[D][d] = Wouti[((size_t)D * HH + h) * HD + d];
    }
    __syncthreads();

    for (int c = 0; c < NC; c++) {
        size_t base = ((size_t)(b * LL + c * CH) * HH + h) * HD;
        for (int i = tid; i < CH * HD; i += 128) {
            int t = i >> 6, d = i & 63;
            size_t off = base + (size_t)t * (HH * HD) + d;
            sq[t][d] = qa[off];
            sk[t][d] = ka[off];
            sv[t][d] = va[off];
        }
        if (tid < CH)
            lr1[tid] = lrb[((size_t)(b * LL + c * CH + tid) * HH + h) * 2 + 1];
        if (tid == 16)
            lr_in_s = lrb[((size_t)(b * LL + c * CH) * HH + h) * 2 + 0];
        __syncthreads();

        // ---- s_k = k_t . W_in, s_q = q_t . W_in ; softmax over D (=4) ----
        {
            int half = tid & 1, idx = tid >> 1;
            int D = idx & 3, t = idx >> 2;
            int j0 = half * 32;
            float aK = 0.f, aQ = 0.f;
#pragma unroll 8
            for (int j = 0; j < 32; j++) {
                float w = Win[D][j0 + j];
                aK += sk[t][j0 + j] * w;
                aQ += sq[t][j0 + j] * w;
            }
            aK += __shfl_xor_sync(FULL, aK, 1);
            aQ += __shfl_xor_sync(FULL, aQ, 1);
            float mK = aK, mQ = aQ;
            mK = fmaxf(mK, __shfl_xor_sync(FULL, mK, 2));
            mK = fmaxf(mK, __shfl_xor_sync(FULL, mK, 4));
            mQ = fmaxf(mQ, __shfl_xor_sync(FULL, mQ, 2));
            mQ = fmaxf(mQ, __shfl_xor_sync(FULL, mQ, 4));
            float eK = expf(aK - mK), eQ = expf(aQ - mQ);
            float sK = eK, sQ = eQ;
            sK += __shfl_xor_sync(FULL, sK, 2); sK += __shfl_xor_sync(FULL, sK, 4);
            sQ += __shfl_xor_sync(FULL, sQ, 2); sQ += __shfl_xor_sync(FULL, sQ, 4);
            if (half == 0) {
                kh[t][D] = eK / sK * lr1[t];
                qh[t][D] = eQ / sQ;
            }
        }
        __syncthreads();

        // ---- qk = (q_h k_h^T) * tril ----
        for (int i = tid; i < CH * CH; i += 128) {
            int tq = i >> 4, tk = i & 15;
            float s = 0.f;
            if (tk <= tq) {
#pragma unroll
                for (int D = 0; D < DI; D++) s += qh[tq][D] * kh[tk][D];
            }
            qkm[tq][tk] = s;
        }
        __syncthreads();

        // ---- o = q_h @ W_out + qk @ v ----
        {
            int d = tid & 63, tg = tid >> 6;
            for (int tt = 0; tt < 8; tt++) {
                int t = tg * 8 + tt;
                float acc = 0.f;
#pragma unroll
                for (int D = 0; D < DI; D++) acc += qh[t][D] * Wout[D][d];
                for (int tk = 0; tk <= t; tk++) acc += qkm[t][tk] * sv[tk][d];
                omid[base + (size_t)t * (HH * HD) + d] = acc;
            }
        }
        __syncthreads();

        // ---- W_out += k_h^T v ----
        {
            int d = tid & 63, D0 = (tid >> 6) * 2;
            float a0 = 0.f, a1 = 0.f;
#pragma unroll
            for (int t = 0; t < CH; t++) {
                float vv = sv[t][d];
                a0 += kh[t][D0] * vv;
                a1 += kh[t][D0 + 1] * vv;
            }
            Wout[D0][d] += a0;
            Wout[D0 + 1][d] += a1;
        }
        __syncthreads();

        float lin = lr_in_s, lout = lr1[0];

        // ---- 2 gradient iterations ----
        for (int it = 0; it < 2; it++) {
            {
                int half = tid & 1, idx = tid >> 1;
                int tk = idx & 15, D = idx >> 4;
                int j0 = half * 32;
                float a1v = 0.f, a2v = 0.f;
#pragma unroll 8
                for (int j = 0; j < 32; j++) {
                    a1v += Win[D][j0 + j] * sk[tk][j0 + j];
                    a2v += Wout[D][j0 + j] * sv[tk][j0 + j];
                }
                a1v += __shfl_xor_sync(FULL, a1v, 1);
                a2v += __shfl_xor_sync(FULL, a2v, 1);
                a1v *= 0.125f;
                a2v *= 0.125f;
                float m1 = a1v, m2 = a2v;
#pragma unroll
                for (int msk = 2; msk <= 16; msk <<= 1) {
                    m1 = fmaxf(m1, __shfl_xor_sync(FULL, m1, msk));
                    m2 = fmaxf(m2, __shfl_xor_sync(FULL, m2, msk));
                }
                float e1 = expf(a1v - m1), e2 = expf(a2v - m2);
                float s1 = e1, s2 = e2;
#pragma unroll
                for (int msk = 2; msk <= 16; msk <<= 1) {
                    s1 += __shfl_xor_sync(FULL, s1, msk);
                    s2 += __shfl_xor_sync(FULL, s2, msk);
                }
                if (half == 0) {
                    p1[D][tk] = e1 / s1;   // softmax(W_in . k / 8)
                    p2[D][tk] = e2 / s2;   // softmax(W_out . v / 8)
                }
            }
            __syncthreads();
            {
                int d = tid & 63, D0 = (tid >> 6) * 2;
                float go0 = 0.f, go1 = 0.f, gi0 = 0.f, gi1 = 0.f;
#pragma unroll
                for (int tk = 0; tk < CH; tk++) {
                    float kk = sk[tk][d], vv = sv[tk][d];
                    go0 += p1[D0][tk] * vv;
                    go1 += p1[D0 + 1][tk] * vv;
                    gi0 += p2[D0][tk] * kk;
                    gi1 += p2[D0 + 1][tk] * kk;
                }
                Win[D0][d]      += lin * gi0;
                Win[D0 + 1][d]  += lin * gi1;
                Wout[D0][d]     += lout * go0;
                Wout[D0 + 1][d] += lout * go1;
            }
            __syncthreads();
        }
    }
}

// ---------------- launch ---------------------------------------------------
extern "C" void kernel_launch(void* const* d_in, const int* in_sizes, int n_in,
                              void* d_out, int out_size) {
    const float* hs  = (const float*)d_in[0];
    const float* Wq  = (const float*)d_in[1];
    const float* Wk  = (const float*)d_in[2];
    const float* Wv  = (const float*)d_in[3];
    const float* Wlr = (const float*)d_in[4];
    const float* Wg  = (const float*)d_in[5];
    const float* Wo  = (const float*)d_in[6];
    const float* cq  = (const float*)d_in[7];
    const float* ck  = (const float*)d_in[8];
    const float* cv  = (const float*)d_in[9];
    const float* Wini  = (const float*)d_in[10];
    const float* Wouti = (const float*)d_in[11];
    const float* lng = (const float*)d_in[12];
    const float* lnb = (const float*)d_in[13];

    float *b0, *b1, *b2, *b3, *b4, *lr;
    cudaGetSymbolAddress((void**)&b0, g_b0);
    cudaGetSymbolAddress((void**)&b1, g_b1);
    cudaGetSymbolAddress((void**)&b2, g_b2);
    cudaGetSymbolAddress((void**)&b3, g_b3);
    cudaGetSymbolAddress((void**)&b4, g_b4);
    cudaGetSymbolAddress((void**)&lr, g_lr);

    dim3 ggrid(DIMN / 128, MTOT / 128);
    // projections
    sgemm_nt<<<ggrid, 256>>>(hs, Wq, b0, MTOT, DIMN, DIMN);   // qlin
    sgemm_nt<<<ggrid, 256>>>(hs, Wk, b1, MTOT, DIMN, DIMN);   // klin
    sgemm_nt<<<ggrid, 256>>>(hs, Wv, b2, MTOT, DIMN, DIMN);   // vlin
    sgemm_nt<<<ggrid, 256>>>(hs, Wg, b3, MTOT, DIMN, DIMN);   // gate
    lr_gemm<<<MTOT / 8, 256>>>(hs, Wlr, lr);

    // conv + act (chain-reuse: b0->b4, b1->b0, b2->b1)
    conv_act<true><<<MTOT, 256>>>(b0, cq, b4);   // q
    conv_act<true><<<MTOT, 256>>>(b1, ck, b0);   // k
    conv_act<false><<<MTOT, 256>>>(b2, cv, b1);  // v

    // sequential scan: writes omid into b2
    scan_kernel<<<BB * HH, 128>>>(b4, b0, b1, lr, Wini, Wouti, b2);

    // layernorm + gate, then output projection
    ln_gate<<<MTOT, 256>>>(b2, b3, lng, lnb);
    sgemm_nt<<<ggrid, 256>>>(b2, Wo, (float*)d_out, MTOT, DIMN, DIMN);
}

// round 5
// speedup vs baseline: 1.6213x; 1.6213x over previous
#include <cuda_runtime.h>
#include <cuda_bf16.h>
#include <math.h>
#include <cstdint>

#define BB   4
#define LL   4096
#define DIMN 1024
#define HH   16
#define HD   64
#define DI   4
#define CH   16
#define NC   (LL / CH)
#define MTOT (BB * LL)

// ---------------- scratch (no cudaMalloc allowed) --------------------------
__device__ float g_b0[(size_t)MTOT * DIMN];
__device__ float g_b1[(size_t)MTOT * DIMN];
__device__ float g_b2[(size_t)MTOT * DIMN];
__device__ float g_b3[(size_t)MTOT * DIMN];
__device__ float g_b4[(size_t)MTOT * DIMN];
__device__ float g_lr[(size_t)MTOT * 32];
// bf16 hi/lo split buffers
__device__ uint4 g_hi[(size_t)MTOT * DIMN / 8];
__device__ uint4 g_lo[(size_t)MTOT * DIMN / 8];
__device__ uint4 g_whi[5ull * DIMN * DIMN / 8];
__device__ uint4 g_wlo[5ull * DIMN * DIMN / 8];

// ================= fp32 -> bf16 hi/lo split ================================
__global__ __launch_bounds__(256) void split_f32(const float4* __restrict__ x,
                                                 uint4* __restrict__ hi,
                                                 uint4* __restrict__ lo, int n8) {
    int i = blockIdx.x * 256 + threadIdx.x;
    if (i >= n8) return;
    float4 a = x[2 * i], b = x[2 * i + 1];
    float v[8] = {a.x, a.y, a.z, a.w, b.x, b.y, b.z, b.w};
    uint32_t h[8], l[8];
#pragma unroll
    for (int j = 0; j < 8; j++) {
        __nv_bfloat16 hh = __float2bfloat16_rn(v[j]);
        float r = v[j] - __bfloat162float(hh);
        h[j] = (uint32_t)__bfloat16_as_ushort(hh);
        l[j] = (uint32_t)__bfloat16_as_ushort(__float2bfloat16_rn(r));
    }
    hi[i] = make_uint4(h[0] | (h[1] << 16), h[2] | (h[3] << 16),
                       h[4] | (h[5] << 16), h[6] | (h[7] << 16));
    lo[i] = make_uint4(l[0] | (l[1] << 16), l[2] | (l[3] << 16),
                       l[4] | (l[5] << 16), l[6] | (l[7] << 16));
}

// ================= mma.sync bf16-split GEMM ================================
// C[M,N] = A[M,K] @ B[N,K]^T (fp32 accuracy via Ahi*Bhi + Ahi*Blo + Alo*Bhi)
// Block 128x128, BK=32 bf16, 256 thr, warp tile 32x64, cp.async double buffer.
#define NKCH  (DIMN / 32)      // 32 K-chunks
#define PITCHW 20              // smem row pitch in 32-bit words (40 bf16, 80B)
#define OPSZ  (128 * 80)       // bytes per operand tile (10240)
#define STGSZ (4 * OPSZ)       // 40960
#define SMEM_GEMM (2 * STGSZ)  // 81920

__device__ __forceinline__ void cp16(uint32_t dst, const void* src) {
    asm volatile("cp.async.cg.shared.global [%0], [%1], 16;" :: "r"(dst), "l"(src));
}
__device__ __forceinline__ uint32_t smem_u32(const void* p) {
    uint32_t a;
    asm("{ .reg .u64 t; cvta.to.shared.u64 t, %1; cvt.u32.u64 %0, t; }" : "=r"(a) : "l"(p));
    return a;
}
__device__ __forceinline__ void mma_bf16(float4& d, uint32_t a0, uint32_t a1,
                                         uint32_t a2, uint32_t a3,
                                         uint32_t b0, uint32_t b1) {
    asm volatile(
        "mma.sync.aligned.m16n8k16.row.col.f32.bf16.bf16.f32 "
        "{%0,%1,%2,%3}, {%4,%5,%6,%7}, {%8,%9}, {%0,%1,%2,%3};"
        : "+f"(d.x), "+f"(d.y), "+f"(d.z), "+f"(d.w)
        : "r"(a0), "r"(a1), "r"(a2), "r"(a3), "r"(b0), "r"(b1));
}

__device__ __forceinline__ void gemm_load_stage(const uint4* __restrict__ Ahi,
                                                const uint4* __restrict__ Alo,
                                                const uint4* __restrict__ Bhi,
                                                const uint4* __restrict__ Blo,
                                                uint32_t sbase, int stage, int kt,
                                                int bm, int bn, int tid) {
#pragma unroll
    for (int op = 0; op < 4; op++) {
        const uint4* src = (op == 0) ? Ahi : (op == 1) ? Alo : (op == 2) ? Bhi : Blo;
        int r0 = (op < 2) ? bm : bn;
        uint32_t dbase = sbase + stage * STGSZ + op * OPSZ;
#pragma unroll
        for (int i = 0; i < 2; i++) {
            int id = tid + i * 256;
            int row = id >> 2, c = id & 3;
            cp16(dbase + row * 80 + c * 16,
                 src + (size_t)(r0 + row) * 128 + kt * 4 + c);
        }
    }
}

__global__ __launch_bounds__(256)
void gemm_tc(const uint4* __restrict__ Ahi, const uint4* __restrict__ Alo,
             const uint4* __restrict__ Bhi, const uint4* __restrict__ Blo,
             float* __restrict__ C) {
    extern __shared__ char smem[];
    uint32_t sbase = smem_u32(smem);
    const uint32_t* sw = (const uint32_t*)smem;

    int tid = threadIdx.x;
    int wid = tid >> 5, lane = tid & 31;
    int warp_m = wid & 3, warp_n = wid >> 2;       // 4 x 2 warp grid
    int gid = lane >> 2, tig = lane & 3;
    int bm = blockIdx.y * 128, bn = blockIdx.x * 128;

    float4 acc[2][8];
#pragma unroll
    for (int mi = 0; mi < 2; mi++)
#pragma unroll
        for (int j = 0; j < 8; j++) acc[mi][j] = make_float4(0.f, 0.f, 0.f, 0.f);

    gemm_load_stage(Ahi, Alo, Bhi, Blo, sbase, 0, 0, bm, bn, tid);
    asm volatile("cp.async.commit_group;");

    for (int kt = 0; kt < NKCH; kt++) {
        if (kt + 1 < NKCH) {
            gemm_load_stage(Ahi, Alo, Bhi, Blo, sbase, (kt + 1) & 1, kt + 1, bm, bn, tid);
            asm volatile("cp.async.commit_group;");
            asm volatile("cp.async.wait_group 1;");
        } else {
            asm volatile("cp.async.wait_group 0;");
        }
        __syncthreads();

        int st = kt & 1;
        const uint32_t* Ah = sw + (st * STGSZ) / 4;
        const uint32_t* Al = Ah + OPSZ / 4;
        const uint32_t* Bh = Al + OPSZ / 4;
        const uint32_t* Bl = Bh + OPSZ / 4;

#pragma unroll
        for (int k16 = 0; k16 < 2; k16++) {
            int kw = k16 * 8;
            // A fragments (hi + lo) for 2 m16 tiles
            uint32_t ah[2][4], al[2][4];
#pragma unroll
            for (int mi = 0; mi < 2; mi++) {
                int r = warp_m * 32 + mi * 16 + gid;
                ah[mi][0] = Ah[r * PITCHW + tig + kw];
                ah[mi][1] = Ah[(r + 8) * PITCHW + tig + kw];
                ah[mi][2] = Ah[r * PITCHW + tig + 4 + kw];
                ah[mi][3] = Ah[(r + 8) * PITCHW + tig + 4 + kw];
                al[mi][0] = Al[r * PITCHW + tig + kw];
                al[mi][1] = Al[(r + 8) * PITCHW + tig + kw];
                al[mi][2] = Al[r * PITCHW + tig + 4 + kw];
                al[mi][3] = Al[(r + 8) * PITCHW + tig + 4 + kw];
            }
            // B fragments in two halves of 4 n-tiles to limit registers
#pragma unroll
            for (int jj = 0; jj < 2; jj++) {
                uint32_t bh[4][2], bl[4][2];
#pragma unroll
                for (int j = 0; j < 4; j++) {
                    int col = warp_n * 64 + (jj * 4 + j) * 8 + gid;
                    bh[j][0] = Bh[col * PITCHW + tig + kw];
                    bh[j][1] = Bh[col * PITCHW + tig + 4 + kw];
                    bl[j][0] = Bl[col * PITCHW + tig + kw];
                    bl[j][1] = Bl[col * PITCHW + tig + 4 + kw];
                }
#pragma unroll
                for (int mi = 0; mi < 2; mi++)
#pragma unroll
                    for (int j = 0; j < 4; j++) {
                        float4& d = acc[mi][jj * 4 + j];
                        mma_bf16(d, ah[mi][0], ah[mi][1], ah[mi][2], ah[mi][3],
                                 bh[j][0], bh[j][1]);
                        mma_bf16(d, ah[mi][0], ah[mi][1], ah[mi][2], ah[mi][3],
                                 bl[j][0], bl[j][1]);
                        mma_bf16(d, al[mi][0], al[mi][1], al[mi][2], al[mi][3],
                                 bh[j][0], bh[j][1]);
                    }
            }
        }
        __syncthreads();
    }

    // epilogue
#pragma unroll
    for (int mi = 0; mi < 2; mi++) {
        int r0 = bm + warp_m * 32 + mi * 16 + gid;
#pragma unroll
        for (int j = 0; j < 8; j++) {
            int col = bn + warp_n * 64 + j * 8 + 2 * tig;
            float4 d = acc[mi][j];
            *(float2*)&C[(size_t)r0 * DIMN + col]       = make_float2(d.x, d.y);
            *(float2*)&C[(size_t)(r0 + 8) * DIMN + col] = make_float2(d.z, d.w);
        }
    }
}

// ================= small kernels (unchanged from passing round) ============
__global__ __launch_bounds__(256) void lr_gemm(const float* __restrict__ X,
                                               const float* __restrict__ W,
                                               float* __restrict__ out) {
    int r = blockIdx.x * 8 + (threadIdx.x >> 5);
    int n = threadIdx.x & 31;
    const float* x = X + (size_t)r * DIMN;
    const float* w = W + (size_t)n * DIMN;
    float acc = 0.f;
    for (int k = 0; k < DIMN; k += 4) {
        float4 xv = *(const float4*)(x + k);
        float4 wv = *(const float4*)(w + k);
        acc += xv.x * wv.x + xv.y * wv.y + xv.z * wv.z + xv.w * wv.w;
    }
    acc += 0.001f;
    float sp = fmaxf(acc, 0.f) + log1pf(expf(-fabsf(acc)));
    out[(size_t)r * 32 + n] = sp;
}

__device__ __forceinline__ float wredsum(float v) {
    for (int m = 16; m > 0; m >>= 1) v += __shfl_xor_sync(0xffffffffu, v, m);
    return v;
}

template <bool NORM>
__global__ __launch_bounds__(256) void conv_act(const float* __restrict__ X,
                                                const float* __restrict__ W,
                                                float* __restrict__ out) {
    __shared__ float sval[DIMN];
    __shared__ float rnorm[HH];
    int row = blockIdx.x;
    int l = row & (LL - 1);
    int tid = threadIdx.x;
    int c0 = tid * 4;
    const float4* X4 = (const float4*)X;
    size_t base = (size_t)row * (DIMN / 4) + tid;
    float4 z = make_float4(0.f, 0.f, 0.f, 0.f);
    float4 x3 = X4[base];
    float4 x2 = (l >= 1) ? X4[base - 256] : z;
    float4 x1 = (l >= 2) ? X4[base - 512] : z;
    float4 x0 = (l >= 3) ? X4[base - 768] : z;
    const float4* W4 = (const float4*)W;
    float4 wA = W4[c0 + 0], wB = W4[c0 + 1], wC = W4[c0 + 2], wD = W4[c0 + 3];

    float y0 = x3.x + wA.x * x0.x + wA.y * x1.x + wA.z * x2.x + wA.w * x3.x;
    float y1 = x3.y + wB.x * x0.y + wB.y * x1.y + wB.z * x2.y + wB.w * x3.y;
    float y2 = x3.z + wC.x * x0.z + wC.y * x1.z + wC.z * x2.z + wC.w * x3.z;
    float y3 = x3.w + wD.x * x0.w + wD.y * x1.w + wD.z * x2.w + wD.w * x3.w;
    y0 = y0 / (1.f + expf(-y0));
    y1 = y1 / (1.f + expf(-y1));
    y2 = y2 / (1.f + expf(-y2));
    y3 = y3 / (1.f + expf(-y3));

    if (NORM) {
        sval[c0 + 0] = y0; sval[c0 + 1] = y1; sval[c0 + 2] = y2; sval[c0 + 3] = y3;
        __syncthreads();
        int wId = tid >> 5, lane = tid & 31;
        for (int h = wId; h < HH; h += 8) {
            float a = sval[h * 64 + lane];
            float b = sval[h * 64 + lane + 32];
            float s = wredsum(a * a + b * b);
            if (lane == 0) rnorm[h] = rsqrtf(s);
        }
        __syncthreads();
        float rn = rnorm[tid >> 4];
        y0 *= rn; y1 *= rn; y2 *= rn; y3 *= rn;
    }
    ((float4*)out)[base] = make_float4(y0, y1, y2, y3);
}

__global__ __launch_bounds__(256) void ln_gate(float* __restrict__ o,
                                               const float* __restrict__ gate,
                                               const float* __restrict__ lng,
                                               const float* __restrict__ lnb) {
    __shared__ float sval[DIMN];
    __shared__ float smu[HH], srs[HH];
    int row = blockIdx.x;
    int tid = threadIdx.x;
    size_t base = (size_t)row * (DIMN / 4) + tid;
    float4 y = ((const float4*)o)[base];
    int c0 = tid * 4;
    sval[c0 + 0] = y.x; sval[c0 + 1] = y.y; sval[c0 + 2] = y.z; sval[c0 + 3] = y.w;
    __syncthreads();
    int wId = tid >> 5, lane = tid & 31;
    for (int h = wId; h < HH; h += 8) {
        float a = sval[h * 64 + lane];
        float b = sval[h * 64 + lane + 32];
        float s = wredsum(a + b);
        float ss = wredsum(a * a + b * b);
        if (lane == 0) {
            float mu = s * (1.f / 64.f);
            float var = ss * (1.f / 64.f) - mu * mu;
            smu[h] = mu;
            srs[h] = rsqrtf(var + 1e-5f);
        }
    }
    __syncthreads();
    int h = tid >> 4;
    float mu = smu[h], rs = srs[h];
    int d0 = c0 & 63;
    float4 gv = ((const float4*)gate)[base];
    float4 lg = ((const float4*)lng)[d0 >> 2];
    float4 lb = ((const float4*)lnb)[d0 >> 2];
    float4 r;
    r.x = ((y.x - mu) * rs * lg.x + lb.x) * gv.x;
    r.y = ((y.y - mu) * rs * lg.y + lb.y) * gv.y;
    r.z = ((y.z - mu) * rs * lg.z + lb.z) * gv.z;
    r.w = ((y.w - mu) * rs * lg.w + lb.w) * gv.w;
    ((float4*)o)[base] = r;
}

// ---------------- sequential chunk scan (unchanged) ------------------------
__global__ __launch_bounds__(128) void scan_kernel(const float* __restrict__ qa,
                                                   const float* __restrict__ ka,
                                                   const float* __restrict__ va,
                                                   const float* __restrict__ lrb,
                                                   const float* __restrict__ Wini,
                                                   const float* __restrict__ Wouti,
                                                   float* __restrict__ omid) {
    __shared__ float sq[CH][HD + 1], sk[CH][HD + 1], sv[CH][HD + 1];
    __shared__ float Win[DI][HD + 1], Wout[DI][HD + 1];
    __shared__ float kh[CH][DI + 1], qh[CH][DI + 1];
    __shared__ float qkm[CH][CH + 1];
    __shared__ float p1[DI][CH + 1], p2[DI][CH + 1];
    __shared__ float lr1[CH];
    __shared__ float lr_in_s;

    int blk = blockIdx.x;
    int b = blk >> 4, h = blk & 15;
    int tid = threadIdx.x;
    const unsigned FULL = 0xffffffffu;

    for (int i = tid; i < DI * HD; i += 128) {
        int D = i >> 6, d = i & 63;
        Win[D][d]  = Wini[((size_t)D * HH + h) * HD + d];
        Wout[D][d] = Wouti[((size_t)D * HH + h) * HD + d];
    }
    __syncthreads();

    for (int c = 0; c < NC; c++) {
        size_t base = ((size_t)(b * LL + c * CH) * HH + h) * HD;
        for (int i = tid; i < CH * HD; i += 128) {
            int t = i >> 6, d = i & 63;
            size_t off = base + (size_t)t * (HH * HD) + d;
            sq[t][d] = qa[off];
            sk[t][d] = ka[off];
            sv[t][d] = va[off];
        }
        if (tid < CH)
            lr1[tid] = lrb[((size_t)(b * LL + c * CH + tid) * HH + h) * 2 + 1];
        if (tid == 16)
            lr_in_s = lrb[((size_t)(b * LL + c * CH) * HH + h) * 2 + 0];
        __syncthreads();

        {
            int half = tid & 1, idx = tid >> 1;
            int D = idx & 3, t = idx >> 2;
            int j0 = half * 32;
            float aK = 0.f, aQ = 0.f;
#pragma unroll 8
            for (int j = 0; j < 32; j++) {
                float w = Win[D][j0 + j];
                aK += sk[t][j0 + j] * w;
                aQ += sq[t][j0 + j] * w;
            }
            aK += __shfl_xor_sync(FULL, aK, 1);
            aQ += __shfl_xor_sync(FULL, aQ, 1);
            float mK = aK, mQ = aQ;
            mK = fmaxf(mK, __shfl_xor_sync(FULL, mK, 2));
            mK = fmaxf(mK, __shfl_xor_sync(FULL, mK, 4));
            mQ = fmaxf(mQ, __shfl_xor_sync(FULL, mQ, 2));
            mQ = fmaxf(mQ, __shfl_xor_sync(FULL, mQ, 4));
            float eK = expf(aK - mK), eQ = expf(aQ - mQ);
            float sK = eK, sQ = eQ;
            sK += __shfl_xor_sync(FULL, sK, 2); sK += __shfl_xor_sync(FULL, sK, 4);
            sQ += __shfl_xor_sync(FULL, sQ, 2); sQ += __shfl_xor_sync(FULL, sQ, 4);
            if (half == 0) {
                kh[t][D] = eK / sK * lr1[t];
                qh[t][D] = eQ / sQ;
            }
        }
        __syncthreads();

        for (int i = tid; i < CH * CH; i += 128) {
            int tq = i >> 4, tk = i & 15;
            float s = 0.f;
            if (tk <= tq) {
#pragma unroll
                for (int D = 0; D < DI; D++) s += qh[tq][D] * kh[tk][D];
            }
            qkm[tq][tk] = s;
        }
        __syncthreads();

        {
            int d = tid & 63, tg = tid >> 6;
            for (int tt = 0; tt < 8; tt++) {
                int t = tg * 8 + tt;
                float acc = 0.f;
#pragma unroll
                for (int D = 0; D < DI; D++) acc += qh[t][D] * Wout[D][d];
                for (int tk = 0; tk <= t; tk++) acc += qkm[t][tk] * sv[tk][d];
                omid[base + (size_t)t * (HH * HD) + d] = acc;
            }
        }
        __syncthreads();

        {
            int d = tid & 63, D0 = (tid >> 6) * 2;
            float a0 = 0.f, a1 = 0.f;
#pragma unroll
            for (int t = 0; t < CH; t++) {
                float vv = sv[t][d];
                a0 += kh[t][D0] * vv;
                a1 += kh[t][D0 + 1] * vv;
            }
            Wout[D0][d] += a0;
            Wout[D0 + 1][d] += a1;
        }
        __syncthreads();

        float lin = lr_in_s, lout = lr1[0];

        for (int it = 0; it < 2; it++) {
            {
                int half = tid & 1, idx = tid >> 1;
                int tk = idx & 15, D = idx >> 4;
                int j0 = half * 32;
                float a1v = 0.f, a2v = 0.f;
#pragma unroll 8
                for (int j = 0; j < 32; j++) {
                    a1v += Win[D][j0 + j] * sk[tk][j0 + j];
                    a2v += Wout[D][j0 + j] * sv[tk][j0 + j];
                }
                a1v += __shfl_xor_sync(FULL, a1v, 1);
                a2v += __shfl_xor_sync(FULL, a2v, 1);
                a1v *= 0.125f;
                a2v *= 0.125f;
                float m1 = a1v, m2 = a2v;
#pragma unroll
                for (int msk = 2; msk <= 16; msk <<= 1) {
                    m1 = fmaxf(m1, __shfl_xor_sync(FULL, m1, msk));
                    m2 = fmaxf(m2, __shfl_xor_sync(FULL, m2, msk));
                }
                float e1 = expf(a1v - m1), e2 = expf(a2v - m2);
                float s1 = e1, s2 = e2;
#pragma unroll
                for (int msk = 2; msk <= 16; msk <<= 1) {
                    s1 += __shfl_xor_sync(FULL, s1, msk);
                    s2 += __shfl_xor_sync(FULL, s2, msk);
                }
                if (half == 0) {
                    p1[D][tk] = e1 / s1;
                    p2[D][tk] = e2 / s2;
                }
            }
            __syncthreads();
            {
                int d = tid & 63, D0 = (tid >> 6) * 2;
                float go0 = 0.f, go1 = 0.f, gi0 = 0.f, gi1 = 0.f;
#pragma unroll
                for (int tk = 0; tk < CH; tk++) {
                    float kk = sk[tk][d], vv = sv[tk][d];
                    go0 += p1[D0][tk] * vv;
                    go1 += p1[D0 + 1][tk] * vv;
                    gi0 += p2[D0][tk] * kk;
                    gi1 += p2[D0 + 1][tk] * kk;
                }
                Win[D0][d]      += lin * gi0;
                Win[D0 + 1][d]  += lin * gi1;
                Wout[D0][d]     += lout * go0;
                Wout[D0 + 1][d] += lout * go1;
            }
            __syncthreads();
        }
    }
}

// ---------------- launch ---------------------------------------------------
extern "C" void kernel_launch(void* const* d_in, const int* in_sizes, int n_in,
                              void* d_out, int out_size) {
    const float* hs  = (const float*)d_in[0];
    const float* Wq  = (const float*)d_in[1];
    const float* Wk  = (const float*)d_in[2];
    const float* Wv  = (const float*)d_in[3];
    const float* Wlr = (const float*)d_in[4];
    const float* Wg  = (const float*)d_in[5];
    const float* Wo  = (const float*)d_in[6];
    const float* cq  = (const float*)d_in[7];
    const float* ck  = (const float*)d_in[8];
    const float* cv  = (const float*)d_in[9];
    const float* Wini  = (const float*)d_in[10];
    const float* Wouti = (const float*)d_in[11];
    const float* lng = (const float*)d_in[12];
    const float* lnb = (const float*)d_in[13];

    float *b0, *b1, *b2, *b3, *b4, *lr;
    uint4 *hi, *lo, *whi, *wlo;
    cudaGetSymbolAddress((void**)&b0, g_b0);
    cudaGetSymbolAddress((void**)&b1, g_b1);
    cudaGetSymbolAddress((void**)&b2, g_b2);
    cudaGetSymbolAddress((void**)&b3, g_b3);
    cudaGetSymbolAddress((void**)&b4, g_b4);
    cudaGetSymbolAddress((void**)&lr, g_lr);
    cudaGetSymbolAddress((void**)&hi, g_hi);
    cudaGetSymbolAddress((void**)&lo, g_lo);
    cudaGetSymbolAddress((void**)&whi, g_whi);
    cudaGetSymbolAddress((void**)&wlo, g_wlo);

    cudaFuncSetAttribute(gemm_tc, cudaFuncAttributeMaxDynamicSharedMemorySize, SMEM_GEMM);

    const size_t W8 = (size_t)DIMN * DIMN / 8;
    const int HS8 = MTOT * (DIMN / 8);

    split_f32<<<HS8 / 256, 256>>>((const float4*)hs, hi, lo, HS8);
    split_f32<<<(int)(W8 / 256), 256>>>((const float4*)Wq, whi + 0 * W8, wlo + 0 * W8, (int)W8);
    split_f32<<<(int)(W8 / 256), 256>>>((const float4*)Wk, whi + 1 * W8, wlo + 1 * W8, (int)W8);
    split_f32<<<(int)(W8 / 256), 256>>>((const float4*)Wv, whi + 2 * W8, wlo + 2 * W8, (int)W8);
    split_f32<<<(int)(W8 / 256), 256>>>((const float4*)Wg, whi + 3 * W8, wlo + 3 * W8, (int)W8);
    split_f32<<<(int)(W8 / 256), 256>>>((const float4*)Wo, whi + 4 * W8, wlo + 4 * W8, (int)W8);

    dim3 ggrid(DIMN / 128, MTOT / 128);
    gemm_tc<<<ggrid, 256, SMEM_GEMM>>>(hi, lo, whi + 0 * W8, wlo + 0 * W8, b0); // qlin
    gemm_tc<<<ggrid, 256, SMEM_GEMM>>>(hi, lo, whi + 1 * W8, wlo + 1 * W8, b1); // klin
    gemm_tc<<<ggrid, 256, SMEM_GEMM>>>(hi, lo, whi + 2 * W8, wlo + 2 * W8, b2); // vlin
    gemm_tc<<<ggrid, 256, SMEM_GEMM>>>(hi, lo, whi + 3 * W8, wlo + 3 * W8, b3); // gate
    lr_gemm<<<MTOT / 8, 256>>>(hs, Wlr, lr);

    conv_act<true><<<MTOT, 256>>>(b0, cq, b4);   // q
    conv_act<true><<<MTOT, 256>>>(b1, ck, b0);   // k
    conv_act<false><<<MTOT, 256>>>(b2, cv, b1);  // v

    scan_kernel<<<BB * HH, 128>>>(b4, b0, b1, lr, Wini, Wouti, b2);

    ln_gate<<<MTOT, 256>>>(b2, b3, lng, lnb);

    split_f32<<<HS8 / 256, 256>>>((const float4*)b2, hi, lo, HS8);
    gemm_tc<<<ggrid, 256, SMEM_GEMM>>>(hi, lo, whi + 4 * W8, wlo + 4 * W8, (float*)d_out);
}

// round 6
// speedup vs baseline: 1.8224x; 1.1240x over previous
#include <cuda_runtime.h>
#include <cuda_bf16.h>
#include <math.h>
#include <cstdint>

#define BB   4
#define LL   4096
#define DIMN 1024
#define HH   16
#define HD   64
#define DI   4
#define CH   16
#define NC   (LL / CH)
#define MTOT (BB * LL)

// ---------------- scratch (no cudaMalloc allowed) --------------------------
__device__ float g_b0[(size_t)MTOT * DIMN];
__device__ float g_b1[(size_t)MTOT * DIMN];
__device__ float g_b2[(size_t)MTOT * DIMN];
__device__ float g_b3[(size_t)MTOT * DIMN];
__device__ float g_b4[(size_t)MTOT * DIMN];
__device__ float g_lr[(size_t)MTOT * 32];
__device__ uint4 g_hi[(size_t)MTOT * DIMN / 8];
__device__ uint4 g_lo[(size_t)MTOT * DIMN / 8];
__device__ uint4 g_whi[5ull * DIMN * DIMN / 8];
__device__ uint4 g_wlo[5ull * DIMN * DIMN / 8];

// ================= fp32 -> bf16 hi/lo split ================================
__global__ __launch_bounds__(256) void split_f32(const float4* __restrict__ x,
                                                 uint4* __restrict__ hi,
                                                 uint4* __restrict__ lo, int n8) {
    int i = blockIdx.x * 256 + threadIdx.x;
    if (i >= n8) return;
    float4 a = x[2 * i], b = x[2 * i + 1];
    float v[8] = {a.x, a.y, a.z, a.w, b.x, b.y, b.z, b.w};
    uint32_t h[8], l[8];
#pragma unroll
    for (int j = 0; j < 8; j++) {
        __nv_bfloat16 hh = __float2bfloat16_rn(v[j]);
        float r = v[j] - __bfloat162float(hh);
        h[j] = (uint32_t)__bfloat16_as_ushort(hh);
        l[j] = (uint32_t)__bfloat16_as_ushort(__float2bfloat16_rn(r));
    }
    hi[i] = make_uint4(h[0] | (h[1] << 16), h[2] | (h[3] << 16),
                       h[4] | (h[5] << 16), h[6] | (h[7] << 16));
    lo[i] = make_uint4(l[0] | (l[1] << 16), l[2] | (l[3] << 16),
                       l[4] | (l[5] << 16), l[6] | (l[7] << 16));
}

// ================= mma.sync bf16-split GEMM ================================
#define NKCH  (DIMN / 32)
#define OPSZ  (128 * 80)       // bytes per operand tile
#define STGSZ (4 * OPSZ)
#define SMEM_GEMM (2 * STGSZ)  // 81920

__device__ __forceinline__ void cp16(uint32_t dst, const void* src) {
    asm volatile("cp.async.cg.shared.global [%0], [%1], 16;" :: "r"(dst), "l"(src));
}
__device__ __forceinline__ uint32_t smem_u32(const void* p) {
    uint32_t a;
    asm("{ .reg .u64 t; cvta.to.shared.u64 t, %1; cvt.u32.u64 %0, t; }" : "=r"(a) : "l"(p));
    return a;
}
__device__ __forceinline__ void ldsm_x4(uint32_t& r0, uint32_t& r1, uint32_t& r2,
                                        uint32_t& r3, uint32_t addr) {
    asm volatile("ldmatrix.sync.aligned.m8n8.x4.shared.b16 {%0,%1,%2,%3}, [%4];"
                 : "=r"(r0), "=r"(r1), "=r"(r2), "=r"(r3) : "r"(addr));
}
__device__ __forceinline__ void mma_bf16(float4& d, const uint32_t* a,
                                         uint32_t b0, uint32_t b1) {
    asm volatile(
        "mma.sync.aligned.m16n8k16.row.col.f32.bf16.bf16.f32 "
        "{%0,%1,%2,%3}, {%4,%5,%6,%7}, {%8,%9}, {%0,%1,%2,%3};"
        : "+f"(d.x), "+f"(d.y), "+f"(d.z), "+f"(d.w)
        : "r"(a[0]), "r"(a[1]), "r"(a[2]), "r"(a[3]), "r"(b0), "r"(b1));
}

__device__ __forceinline__ void gemm_load_stage(const uint4* __restrict__ Ahi,
                                                const uint4* __restrict__ Alo,
                                                const uint4* __restrict__ Bhi,
                                                const uint4* __restrict__ Blo,
                                                uint32_t sbase, int stage, int kt,
                                                int bm, int bnG, int tid) {
#pragma unroll
    for (int op = 0; op < 4; op++) {
        const uint4* src = (op == 0) ? Ahi : (op == 1) ? Alo : (op == 2) ? Bhi : Blo;
        int r0 = (op < 2) ? bm : bnG;
        uint32_t dbase = sbase + stage * STGSZ + op * OPSZ;
#pragma unroll
        for (int i = 0; i < 2; i++) {
            int id = tid + i * 256;
            int row = id >> 2, c = id & 3;
            cp16(dbase + row * 80 + c * 16,
                 src + (size_t)(r0 + row) * 128 + kt * 4 + c);
        }
    }
}

// C selected per column group of 1024 (fused 4-way projection); bnG = global B row.
__global__ __launch_bounds__(256)
void gemm_tc(const uint4* __restrict__ Ahi, const uint4* __restrict__ Alo,
             const uint4* __restrict__ Bhi, const uint4* __restrict__ Blo,
             float* __restrict__ C0, float* __restrict__ C1,
             float* __restrict__ C2, float* __restrict__ C3) {
    extern __shared__ char smem[];
    uint32_t sbase = smem_u32(smem);

    int tid = threadIdx.x;
    int wid = tid >> 5, lane = tid & 31;
    int warp_m = wid & 3, warp_n = wid >> 2;
    int gid = lane >> 2, tig = lane & 3;
    int bm = blockIdx.y * 128;
    int bnG = blockIdx.x * 128;
    int which = blockIdx.x >> 3;
    int bnC = (blockIdx.x & 7) * 128;
    float* C = (which == 0) ? C0 : (which == 1) ? C1 : (which == 2) ? C2 : C3;

    float4 acc[2][8];
#pragma unroll
    for (int mi = 0; mi < 2; mi++)
#pragma unroll
        for (int j = 0; j < 8; j++) acc[mi][j] = make_float4(0.f, 0.f, 0.f, 0.f);

    gemm_load_stage(Ahi, Alo, Bhi, Blo, sbase, 0, 0, bm, bnG, tid);
    asm volatile("cp.async.commit_group;");

    for (int kt = 0; kt < NKCH; kt++) {
        asm volatile("cp.async.wait_group 0;");
        __syncthreads();
        if (kt + 1 < NKCH) {
            gemm_load_stage(Ahi, Alo, Bhi, Blo, sbase, (kt + 1) & 1, kt + 1, bm, bnG, tid);
            asm volatile("cp.async.commit_group;");
        }

        uint32_t stb = sbase + (kt & 1) * STGSZ;   // Ah base; Al/Bh/Bl at +OPSZ steps
#pragma unroll
        for (int k16 = 0; k16 < 2; k16++) {
            uint32_t kwB = k16 * 32;
            uint32_t ah[2][4], al[2][4];
#pragma unroll
            for (int mi = 0; mi < 2; mi++) {
                uint32_t ra = stb + (uint32_t)(warp_m * 32 + mi * 16 + (lane & 15)) * 80
                              + kwB + (lane >> 4) * 16;
                ldsm_x4(ah[mi][0], ah[mi][1], ah[mi][2], ah[mi][3], ra);
                ldsm_x4(al[mi][0], al[mi][1], al[mi][2], al[mi][3], ra + OPSZ);
            }
#pragma unroll
            for (int half = 0; half < 2; half++) {
                uint32_t bh[4][2], bl[4][2];
#pragma unroll
                for (int p = 0; p < 2; p++) {
                    int tile = half * 4 + p * 2 + (lane >> 4);
                    int khalf = (lane >> 3) & 1;
                    uint32_t rb = stb + 2 * OPSZ
                                  + (uint32_t)(warp_n * 64 + tile * 8 + (lane & 7)) * 80
                                  + kwB + khalf * 16;
                    ldsm_x4(bh[p * 2][0], bh[p * 2][1], bh[p * 2 + 1][0], bh[p * 2 + 1][1], rb);
                    ldsm_x4(bl[p * 2][0], bl[p * 2][1], bl[p * 2 + 1][0], bl[p * 2 + 1][1],
                            rb + OPSZ);
                }
#pragma unroll
                for (int mi = 0; mi < 2; mi++)
#pragma unroll
                    for (int j = 0; j < 4; j++) {
                        float4& d = acc[mi][half * 4 + j];
                        mma_bf16(d, ah[mi], bh[j][0], bh[j][1]);
                        mma_bf16(d, ah[mi], bl[j][0], bl[j][1]);
                        mma_bf16(d, al[mi], bh[j][0], bh[j][1]);
                    }
            }
        }
        __syncthreads();
    }

#pragma unroll
    for (int mi = 0; mi < 2; mi++) {
        int r0 = bm + warp_m * 32 + mi * 16 + gid;
#pragma unroll
        for (int j = 0; j < 8; j++) {
            int col = bnC + warp_n * 64 + j * 8 + 2 * tig;
            float4 d = acc[mi][j];
            *(float2*)&C[(size_t)r0 * DIMN + col]       = make_float2(d.x, d.y);
            *(float2*)&C[(size_t)(r0 + 8) * DIMN + col] = make_float2(d.z, d.w);
        }
    }
}

// ================= small kernels ===========================================
__global__ __launch_bounds__(256) void lr_gemm(const float* __restrict__ X,
                                               const float* __restrict__ W,
                                               float* __restrict__ out) {
    int r = blockIdx.x * 8 + (threadIdx.x >> 5);
    int n = threadIdx.x & 31;
    const float* x = X + (size_t)r * DIMN;
    const float* w = W + (size_t)n * DIMN;
    float acc = 0.f;
    for (int k = 0; k < DIMN; k += 4) {
        float4 xv = *(const float4*)(x + k);
        float4 wv = *(const float4*)(w + k);
        acc += xv.x * wv.x + xv.y * wv.y + xv.z * wv.z + xv.w * wv.w;
    }
    acc += 0.001f;
    float sp = fmaxf(acc, 0.f) + log1pf(expf(-fabsf(acc)));
    out[(size_t)r * 32 + n] = sp;
}

__device__ __forceinline__ float wredsum(float v) {
    for (int m = 16; m > 0; m >>= 1) v += __shfl_xor_sync(0xffffffffu, v, m);
    return v;
}

template <bool NORM>
__global__ __launch_bounds__(256) void conv_act(const float* __restrict__ X,
                                                const float* __restrict__ W,
                                                float* __restrict__ out) {
    __shared__ float sval[DIMN];
    __shared__ float rnorm[HH];
    int row = blockIdx.x;
    int l = row & (LL - 1);
    int tid = threadIdx.x;
    int c0 = tid * 4;
    const float4* X4 = (const float4*)X;
    size_t base = (size_t)row * (DIMN / 4) + tid;
    float4 z = make_float4(0.f, 0.f, 0.f, 0.f);
    float4 x3 = X4[base];
    float4 x2 = (l >= 1) ? X4[base - 256] : z;
    float4 x1 = (l >= 2) ? X4[base - 512] : z;
    float4 x0 = (l >= 3) ? X4[base - 768] : z;
    const float4* W4 = (const float4*)W;
    float4 wA = W4[c0 + 0], wB = W4[c0 + 1], wC = W4[c0 + 2], wD = W4[c0 + 3];

    float y0 = x3.x + wA.x * x0.x + wA.y * x1.x + wA.z * x2.x + wA.w * x3.x;
    float y1 = x3.y + wB.x * x0.y + wB.y * x1.y + wB.z * x2.y + wB.w * x3.y;
    float y2 = x3.z + wC.x * x0.z + wC.y * x1.z + wC.z * x2.z + wC.w * x3.z;
    float y3 = x3.w + wD.x * x0.w + wD.y * x1.w + wD.z * x2.w + wD.w * x3.w;
    y0 = y0 / (1.f + expf(-y0));
    y1 = y1 / (1.f + expf(-y1));
    y2 = y2 / (1.f + expf(-y2));
    y3 = y3 / (1.f + expf(-y3));

    if (NORM) {
        sval[c0 + 0] = y0; sval[c0 + 1] = y1; sval[c0 + 2] = y2; sval[c0 + 3] = y3;
        __syncthreads();
        int wId = tid >> 5, lane = tid & 31;
        for (int h = wId; h < HH; h += 8) {
            float a = sval[h * 64 + lane];
            float b = sval[h * 64 + lane + 32];
            float s = wredsum(a * a + b * b);
            if (lane == 0) rnorm[h] = rsqrtf(s);
        }
        __syncthreads();
        float rn = rnorm[tid >> 4];
        y0 *= rn; y1 *= rn; y2 *= rn; y3 *= rn;
    }
    ((float4*)out)[base] = make_float4(y0, y1, y2, y3);
}

__global__ __launch_bounds__(256) void ln_gate(float* __restrict__ o,
                                               const float* __restrict__ gate,
                                               const float* __restrict__ lng,
                                               const float* __restrict__ lnb) {
    __shared__ float sval[DIMN];
    __shared__ float smu[HH], srs[HH];
    int row = blockIdx.x;
    int tid = threadIdx.x;
    size_t base = (size_t)row * (DIMN / 4) + tid;
    float4 y = ((const float4*)o)[base];
    int c0 = tid * 4;
    sval[c0 + 0] = y.x; sval[c0 + 1] = y.y; sval[c0 + 2] = y.z; sval[c0 + 3] = y.w;
    __syncthreads();
    int wId = tid >> 5, lane = tid & 31;
    for (int h = wId; h < HH; h += 8) {
        float a = sval[h * 64 + lane];
        float b = sval[h * 64 + lane + 32];
        float s = wredsum(a + b);
        float ss = wredsum(a * a + b * b);
        if (lane == 0) {
            float mu = s * (1.f / 64.f);
            float var = ss * (1.f / 64.f) - mu * mu;
            smu[h] = mu;
            srs[h] = rsqrtf(var + 1e-5f);
        }
    }
    __syncthreads();
    int h = tid >> 4;
    float mu = smu[h], rs = srs[h];
    int d0 = c0 & 63;
    float4 gv = ((const float4*)gate)[base];
    float4 lg = ((const float4*)lng)[d0 >> 2];
    float4 lb = ((const float4*)lnb)[d0 >> 2];
    float4 r;
    r.x = ((y.x - mu) * rs * lg.x + lb.x) * gv.x;
    r.y = ((y.y - mu) * rs * lg.y + lb.y) * gv.y;
    r.z = ((y.z - mu) * rs * lg.z + lb.z) * gv.z;
    r.w = ((y.w - mu) * rs * lg.w + lb.w) * gv.w;
    ((float4*)o)[base] = r;
}

// ---------------- sequential chunk scan with cp.async double buffering -----
#define SROW (HD + 4)
__global__ __launch_bounds__(128) void scan_kernel(const float* __restrict__ qa,
                                                   const float* __restrict__ ka,
                                                   const float* __restrict__ va,
                                                   const float* __restrict__ lrb,
                                                   const float* __restrict__ Wini,
                                                   const float* __restrict__ Wouti,
                                                   float* __restrict__ omid) {
    __shared__ float sq[2][CH][SROW], sk[2][CH][SROW], sv[2][CH][SROW];
    __shared__ float Win[DI][HD + 1], Wout[DI][HD + 1];
    __shared__ float kh[CH][DI + 1], qh[CH][DI + 1];
    __shared__ float qkm[CH][CH + 1];
    __shared__ float p1[DI][CH + 1], p2[DI][CH + 1];
    __shared__ float lr1[2][CH];
    __shared__ float lrin[2];

    int blk = blockIdx.x;
    int b = blk >> 4, h = blk & 15;
    int tid = threadIdx.x;
    const unsigned FULL = 0xffffffffu;

    uint32_t uq = smem_u32(&sq[0][0][0]);
    uint32_t uk = smem_u32(&sk[0][0][0]);
    uint32_t uv = smem_u32(&sv[0][0][0]);
    const uint32_t BUFB = CH * SROW * 4;   // bytes per buffer

    for (int i = tid; i < DI * HD; i += 128) {
        int D = i >> 6, d = i & 63;
        Win[D][d]  = Wini[((size_t)D * HH + h) * HD + d];
        Wout[D][d] = Wouti[((size_t)D * HH + h) * HD + d];
    }

    // prologue: chunk 0 qkv via cp.async; lr via regular loads
    {
        size_t gb = ((size_t)(b * LL) * HH + h) * HD;
#pragma unroll
        for (int i = 0; i < 2; i++) {
            int e = tid + i * 128;
            int t = e >> 4, q4 = e & 15;
            uint32_t so = (uint32_t)t * (SROW * 4) + q4 * 16;
            size_t go = (gb + (size_t)t * (HH * HD)) * 4 + q4 * 16;
            cp16(uq + so, (const char*)qa + go);
            cp16(uk + so, (const char*)ka + go);
            cp16(uv + so, (const char*)va + go);
        }
        asm volatile("cp.async.commit_group;");
        if (tid < CH)
            lr1[0][tid] = lrb[((size_t)(b * LL + tid) * HH + h) * 2 + 1];
        if (tid == 16)
            lrin[0] = lrb[((size_t)(b * LL) * HH + h) * 2 + 0];
    }

    for (int c = 0; c < NC; c++) {
        int cur = c & 1, nxt = cur ^ 1;
        size_t base = ((size_t)(b * LL + c * CH) * HH + h) * HD;
        float lrn = 0.f, lrinn = 0.f;

        if (c + 1 < NC) {
            size_t gb = base + (size_t)CH * (HH * HD);
#pragma unroll
            for (int i = 0; i < 2; i++) {
                int e = tid + i * 128;
                int t = e >> 4, q4 = e & 15;
                uint32_t so = nxt * BUFB + (uint32_t)t * (SROW * 4) + q4 * 16;
                size_t go = (gb + (size_t)t * (HH * HD)) * 4 + q4 * 16;
                cp16(uq + so, (const char*)qa + go);
                cp16(uk + so, (const char*)ka + go);
                cp16(uv + so, (const char*)va + go);
            }
            asm volatile("cp.async.commit_group;");
            if (tid < CH)
                lrn = lrb[((size_t)(b * LL + (c + 1) * CH + tid) * HH + h) * 2 + 1];
            if (tid == 16)
                lrinn = lrb[((size_t)(b * LL + (c + 1) * CH) * HH + h) * 2 + 0];
            asm volatile("cp.async.wait_group 1;");
        } else {
            asm volatile("cp.async.wait_group 0;");
        }
        __syncthreads();   // chunk c data visible; prior chunk compute done

        // ---- s_k = k . W_in, s_q = q . W_in ; softmax over D ----
        {
            int half = tid & 1, idx = tid >> 1;
            int D = idx & 3, t = idx >> 2;
            int j0 = half * 32;
            float aK = 0.f, aQ = 0.f;
#pragma unroll 8
            for (int j = 0; j < 32; j++) {
                float w = Win[D][j0 + j];
                aK += sk[cur][t][j0 + j] * w;
                aQ += sq[cur][t][j0 + j] * w;
            }
            aK += __shfl_xor_sync(FULL, aK, 1);
            aQ += __shfl_xor_sync(FULL, aQ, 1);
            float mK = aK, mQ = aQ;
            mK = fmaxf(mK, __shfl_xor_sync(FULL, mK, 2));
            mK = fmaxf(mK, __shfl_xor_sync(FULL, mK, 4));
            mQ = fmaxf(mQ, __shfl_xor_sync(FULL, mQ, 2));
            mQ = fmaxf(mQ, __shfl_xor_sync(FULL, mQ, 4));
            float eK = expf(aK - mK), eQ = expf(aQ - mQ);
            float sK = eK, sQ = eQ;
            sK += __shfl_xor_sync(FULL, sK, 2); sK += __shfl_xor_sync(FULL, sK, 4);
            sQ += __shfl_xor_sync(FULL, sQ, 2); sQ += __shfl_xor_sync(FULL, sQ, 4);
            if (half == 0) {
                kh[t][D] = eK / sK * lr1[cur][t];
                qh[t][D] = eQ / sQ;
            }
        }
        __syncthreads();

        // ---- qk = (q_h k_h^T) * tril ----
        for (int i = tid; i < CH * CH; i += 128) {
            int tq = i >> 4, tk = i & 15;
            float s = 0.f;
            if (tk <= tq) {
#pragma unroll
                for (int D = 0; D < DI; D++) s += qh[tq][D] * kh[tk][D];
            }
            qkm[tq][tk] = s;
        }
        __syncthreads();

        // ---- o = q_h @ W_out + qk @ v ----
        {
            int d = tid & 63, tg = tid >> 6;
            for (int tt = 0; tt < 8; tt++) {
                int t = tg * 8 + tt;
                float acc = 0.f;
#pragma unroll
                for (int D = 0; D < DI; D++) acc += qh[t][D] * Wout[D][d];
                for (int tk = 0; tk <= t; tk++) acc += qkm[t][tk] * sv[cur][tk][d];
                omid[base + (size_t)t * (HH * HD) + d] = acc;
            }
        }
        __syncthreads();

        // ---- W_out += k_h^T v ----
        {
            int d = tid & 63, D0 = (tid >> 6) * 2;
            float a0 = 0.f, a1 = 0.f;
#pragma unroll
            for (int t = 0; t < CH; t++) {
                float vv = sv[cur][t][d];
                a0 += kh[t][D0] * vv;
                a1 += kh[t][D0 + 1] * vv;
            }
            Wout[D0][d] += a0;
            Wout[D0 + 1][d] += a1;
        }
        __syncthreads();

        float lin = lrin[cur], lout = lr1[cur][0];

        // ---- 2 gradient iterations ----
        for (int it = 0; it < 2; it++) {
            {
                int half = tid & 1, idx = tid >> 1;
                int tk = idx & 15, D = idx >> 4;
                int j0 = half * 32;
                float a1v = 0.f, a2v = 0.f;
#pragma unroll 8
                for (int j = 0; j < 32; j++) {
                    a1v += Win[D][j0 + j] * sk[cur][tk][j0 + j];
                    a2v += Wout[D][j0 + j] * sv[cur][tk][j0 + j];
                }
                a1v += __shfl_xor_sync(FULL, a1v, 1);
                a2v += __shfl_xor_sync(FULL, a2v, 1);
                a1v *= 0.125f;
                a2v *= 0.125f;
                float m1 = a1v, m2 = a2v;
#pragma unroll
                for (int msk = 2; msk <= 16; msk <<= 1) {
                    m1 = fmaxf(m1, __shfl_xor_sync(FULL, m1, msk));
                    m2 = fmaxf(m2, __shfl_xor_sync(FULL, m2, msk));
                }
                float e1 = expf(a1v - m1), e2 = expf(a2v - m2);
                float s1 = e1, s2 = e2;
#pragma unroll
                for (int msk = 2; msk <= 16; msk <<= 1) {
                    s1 += __shfl_xor_sync(FULL, s1, msk);
                    s2 += __shfl_xor_sync(FULL, s2, msk);
                }
                if (half == 0) {
                    p1[D][tk] = e1 / s1;
                    p2[D][tk] = e2 / s2;
                }
            }
            __syncthreads();
            {
                int d = tid & 63, D0 = (tid >> 6) * 2;
                float go0 = 0.f, go1 = 0.f, gi0 = 0.f, gi1 = 0.f;
#pragma unroll
                for (int tk = 0; tk < CH; tk++) {
                    float kk = sk[cur][tk][d], vv = sv[cur][tk][d];
                    go0 += p1[D0][tk] * vv;
                    go1 += p1[D0 + 1][tk] * vv;
                    gi0 += p2[D0][tk] * kk;
                    gi1 += p2[D0 + 1][tk] * kk;
                }
                Win[D0][d]      += lin * gi0;
                Win[D0 + 1][d]  += lin * gi1;
                Wout[D0][d]     += lout * go0;
                Wout[D0 + 1][d] += lout * go1;
            }
            __syncthreads();
        }

        // stash prefetched lr for next chunk (ordered by next top-of-loop barrier)
        if (c + 1 < NC) {
            if (tid < CH) lr1[nxt][tid] = lrn;
            if (tid == 16) lrin[nxt] = lrinn;
        }
    }
}

// ---------------- launch ---------------------------------------------------
extern "C" void kernel_launch(void* const* d_in, const int* in_sizes, int n_in,
                              void* d_out, int out_size) {
    const float* hs  = (const float*)d_in[0];
    const float* Wq  = (const float*)d_in[1];
    const float* Wk  = (const float*)d_in[2];
    const float* Wv  = (const float*)d_in[3];
    const float* Wlr = (const float*)d_in[4];
    const float* Wg  = (const float*)d_in[5];
    const float* Wo  = (const float*)d_in[6];
    const float* cq  = (const float*)d_in[7];
    const float* ck  = (const float*)d_in[8];
    const float* cv  = (const float*)d_in[9];
    const float* Wini  = (const float*)d_in[10];
    const float* Wouti = (const float*)d_in[11];
    const float* lng = (const float*)d_in[12];
    const float* lnb = (const float*)d_in[13];

    float *b0, *b1, *b2, *b3, *b4, *lr;
    uint4 *hi, *lo, *whi, *wlo;
    cudaGetSymbolAddress((void**)&b0, g_b0);
    cudaGetSymbolAddress((void**)&b1, g_b1);
    cudaGetSymbolAddress((void**)&b2, g_b2);
    cudaGetSymbolAddress((void**)&b3, g_b3);
    cudaGetSymbolAddress((void**)&b4, g_b4);
    cudaGetSymbolAddress((void**)&lr, g_lr);
    cudaGetSymbolAddress((void**)&hi, g_hi);
    cudaGetSymbolAddress((void**)&lo, g_lo);
    cudaGetSymbolAddress((void**)&whi, g_whi);
    cudaGetSymbolAddress((void**)&wlo, g_wlo);

    cudaFuncSetAttribute(gemm_tc, cudaFuncAttributeMaxDynamicSharedMemorySize, SMEM_GEMM);

    const size_t W8 = (size_t)DIMN * DIMN / 8;
    const int HS8 = MTOT * (DIMN / 8);

    // launches 0-4: weight splits (Wq,Wk,Wv,Wg) + hs split
    split_f32<<<(int)(W8 / 256), 256>>>((const float4*)Wq, whi + 0 * W8, wlo + 0 * W8, (int)W8);
    split_f32<<<(int)(W8 / 256), 256>>>((const float4*)Wk, whi + 1 * W8, wlo + 1 * W8, (int)W8);
    split_f32<<<(int)(W8 / 256), 256>>>((const float4*)Wv, whi + 2 * W8, wlo + 2 * W8, (int)W8);
    split_f32<<<(int)(W8 / 256), 256>>>((const float4*)Wg, whi + 3 * W8, wlo + 3 * W8, (int)W8);
    split_f32<<<HS8 / 256, 256>>>((const float4*)hs, hi, lo, HS8);

    // launch 5 (ncu-profiled): fused 4-way projection GEMM, N = 4096
    dim3 fgrid(4 * DIMN / 128, MTOT / 128);
    gemm_tc<<<fgrid, 256, SMEM_GEMM>>>(hi, lo, whi, wlo, b0, b1, b2, b3);

    lr_gemm<<<MTOT / 8, 256>>>(hs, Wlr, lr);
    split_f32<<<(int)(W8 / 256), 256>>>((const float4*)Wo, whi + 4 * W8, wlo + 4 * W8, (int)W8);

    conv_act<true><<<MTOT, 256>>>(b0, cq, b4);   // q
    conv_act<true><<<MTOT, 256>>>(b1, ck, b0);   // k
    conv_act<false><<<MTOT, 256>>>(b2, cv, b1);  // v

    scan_kernel<<<BB * HH, 128>>>(b4, b0, b1, lr, Wini, Wouti, b2);

    ln_gate<<<MTOT, 256>>>(b2, b3, lng, lnb);

    split_f32<<<HS8 / 256, 256>>>((const float4*)b2, hi, lo, HS8);
    dim3 ogrid(DIMN / 128, MTOT / 128);
    gemm_tc<<<ogrid, 256, SMEM_GEMM>>>(hi, lo, whi + 4 * W8, wlo + 4 * W8,
                                       (float*)d_out, (float*)d_out,
                                       (float*)d_out, (float*)d_out);
}